// round 4
// baseline (speedup 1.0000x reference)
#include <cuda_runtime.h>
#include <math.h>

#define B_SZ 256
#define T_ENC 336
#define F_IN 16
#define U_SZ 512
#define G4 2048
#define HORIZON 48

#define NT 256
#define BM 64
#define BN 64
#define BK 16

// ---------------- persistent device scratch (static, allocation-free) ----------------
__device__ float g_out0[(size_t)B_SZ * T_ENC * U_SZ];  // encoder layer0 h_t for all t
__device__ float g_h1[2][B_SZ * U_SZ];                 // layer1 h ping-pong
__device__ float g_c0[B_SZ * U_SZ];
__device__ float g_c1[B_SZ * U_SZ];
__device__ float g_dh0[2][B_SZ * U_SZ];
__device__ float g_x[B_SZ];
__device__ float g_zero[B_SZ * U_SZ];                  // never written: stays zero

__device__ __forceinline__ float sigf(float x) { return 1.0f / (1.0f + expf(-x)); }

// packed fp32 FMA (Blackwell): c.lo += a.lo*b.lo ; c.hi += a.hi*b.hi
#define FMA2(c, a, b) asm("fma.rn.f32x2 %0, %1, %2, %0;" : "+l"(c) : "l"(a), "l"(b))

__device__ __forceinline__ unsigned long long dup2(float v) {
    unsigned long long r;
    unsigned u = __float_as_uint(v);
    asm("mov.b64 %0, {%1, %1};" : "=l"(r) : "r"(u));
    return r;
}

// ---------------------------------------------------------------------------
// Fused LSTM step:
//   z[256, 2048] = A0[256,K0] @ W0 + A1[256,K1] @ W1 + bias
//   i,f,g,o = split(z); c = f*c + i*tanh(g); h = o*tanh(c)
// Block tile: 64 batch rows x (4 gates x 16 units); grid (32, 4).
// GEMM: 256 thr, 4x4 microtile, double-buffered smem, packed f32x2 FMA.
// B smem holds duplicated (b,b) 64-bit pairs so the inner loop has zero packing.
// ---------------------------------------------------------------------------
__global__ __launch_bounds__(NT) void lstm_step(
    const float* __restrict__ A0, int lda0, int K0, const float* __restrict__ W0,
    const float* __restrict__ A1, int lda1, int K1, const float* __restrict__ W1,
    const float* __restrict__ bias,
    float* __restrict__ c_state,
    float* __restrict__ h_out, int ldh)
{
    __shared__ float As[2][BK][BM];                    // 8 KB
    __shared__ unsigned long long Bs[2][BK][BN];       // 16 KB (dup pairs)
    __shared__ float Zs[BM][BN + 1];                   // 16.25 KB

    const int tid = threadIdx.x;
    const int block_m = blockIdx.y * BM;
    const int block_u = blockIdx.x;

    // loader mapping
    const int arow = tid >> 2;           // 0..63 : A row
    const int ak4  = (tid & 3) * 4;      // 0,4,8,12 : A k-offset (float4)
    const int bkk  = tid >> 4;           // 0..15 : B k row
    const int bn4  = (tid & 15) * 4;     // 0..60 : B tile col (float4)
    const int bwcol = (bn4 >> 4) * 512 + block_u * 16 + (bn4 & 15);

    // compute mapping: 4x4 microtile
    const int tx = tid & 15;
    const int ty = tid >> 4;
    const int n0 = tx * 4;
    const int m0 = ty * 4;

    const int tiles0 = (K0 + BK - 1) / BK;
    const int tilesT = tiles0 + (K1 + BK - 1) / BK;

    unsigned long long acc[2][4];
#pragma unroll
    for (int p = 0; p < 2; ++p)
#pragma unroll
        for (int j = 0; j < 4; ++j) acc[p][j] = 0ULL;   // (0.f, 0.f)

    auto fetch = [&](int t, float4& a, float4& w) {
        const float* A; const float* W; int lda, K, kb;
        if (t < tiles0) { A = A0; W = W0; lda = lda0; K = K0; kb = t * BK; }
        else            { A = A1; W = W1; lda = lda1; K = K1; kb = (t - tiles0) * BK; }
        const float* ab = A + (size_t)(block_m + arow) * lda + kb + ak4;
        if (kb + BK <= K) {
            a = *(const float4*)ab;
        } else {
            float t0 = (kb + ak4 + 0 < K) ? ab[0] : 0.f;
            float t1 = (kb + ak4 + 1 < K) ? ab[1] : 0.f;
            float t2 = (kb + ak4 + 2 < K) ? ab[2] : 0.f;
            float t3 = (kb + ak4 + 3 < K) ? ab[3] : 0.f;
            a = make_float4(t0, t1, t2, t3);
        }
        int kg = kb + bkk;
        if (kg < K) w = *(const float4*)(W + (size_t)kg * G4 + bwcol);
        else        w = make_float4(0.f, 0.f, 0.f, 0.f);
    };

    auto stash = [&](int s, const float4& a, const float4& w) {
        As[s][ak4 + 0][arow] = a.x;
        As[s][ak4 + 1][arow] = a.y;
        As[s][ak4 + 2][arow] = a.z;
        As[s][ak4 + 3][arow] = a.w;
        ulonglong2 p01 = make_ulonglong2(dup2(w.x), dup2(w.y));
        ulonglong2 p23 = make_ulonglong2(dup2(w.z), dup2(w.w));
        *(ulonglong2*)&Bs[s][bkk][bn4 + 0] = p01;
        *(ulonglong2*)&Bs[s][bkk][bn4 + 2] = p23;
    };

    auto compute = [&](int s) {
#pragma unroll
        for (int kk = 0; kk < BK; ++kk) {
            // a pairs: (m0,m0+1) and (m0+2,m0+3) — one LDS.128
            ulonglong2 au = *(const ulonglong2*)&As[s][kk][m0];
            // b dup pairs — two LDS.128
            ulonglong2 b01 = *(const ulonglong2*)&Bs[s][kk][n0];
            ulonglong2 b23 = *(const ulonglong2*)&Bs[s][kk][n0 + 2];
            FMA2(acc[0][0], au.x, b01.x);
            FMA2(acc[0][1], au.x, b01.y);
            FMA2(acc[0][2], au.x, b23.x);
            FMA2(acc[0][3], au.x, b23.y);
            FMA2(acc[1][0], au.y, b01.x);
            FMA2(acc[1][1], au.y, b01.y);
            FMA2(acc[1][2], au.y, b23.x);
            FMA2(acc[1][3], au.y, b23.y);
        }
    };

    // ---- double-buffered mainloop ----
    {
        float4 a, w;
        fetch(0, a, w);
        stash(0, a, w);
    }
    __syncthreads();
    int cur = 0;
    for (int t = 0; t < tilesT; ++t) {
        float4 a, w;
        const bool has_next = (t + 1 < tilesT);
        if (has_next) fetch(t + 1, a, w);
        compute(cur);
        if (has_next) {
            stash(cur ^ 1, a, w);
            __syncthreads();
            cur ^= 1;
        }
    }

    // ---- epilogue: z-tile -> smem with bias ----
    const int cwcol = (n0 >> 4) * 512 + block_u * 16 + (n0 & 15);
#pragma unroll
    for (int j = 0; j < 4; ++j) {
        float bb = bias[cwcol + j];
#pragma unroll
        for (int p = 0; p < 2; ++p) {
            unsigned long long v = acc[p][j];
            Zs[m0 + 2 * p + 0][n0 + j] = __uint_as_float((unsigned)v) + bb;
            Zs[m0 + 2 * p + 1][n0 + j] = __uint_as_float((unsigned)(v >> 32)) + bb;
        }
    }
    __syncthreads();

    // ---- gates + state update: each thread does 4 (b,u) pairs ----
    const int uo = tid & 15;
    const int gu = block_u * 16 + uo;
    const int r0 = (tid >> 4) * 4;
#pragma unroll
    for (int i = 0; i < 4; ++i) {
        int br = r0 + i;
        float zi = Zs[br][ 0 + uo];
        float zf = Zs[br][16 + uo];
        float zg = Zs[br][32 + uo];
        float zo = Zs[br][48 + uo];
        float ig = sigf(zi);
        float fg = sigf(zf);
        float gg = tanhf(zg);
        float og = sigf(zo);
        size_t ci = (size_t)(block_m + br) * U_SZ + gu;
        float cn = fg * c_state[ci] + ig * gg;
        c_state[ci] = cn;
        h_out[(size_t)(block_m + br) * ldh + gu] = og * tanhf(cn);
    }
}

// y[b] = h1[b,:] . Wd + bd ; write out[b,HORIZON] column d and next x
__global__ __launch_bounds__(128) void proj_kernel(
    const float* __restrict__ h1, const float* __restrict__ Wd,
    const float* __restrict__ bd, float* __restrict__ x,
    float* __restrict__ out, int d)
{
    int w = (blockIdx.x * blockDim.x + threadIdx.x) >> 5;
    int lane = threadIdx.x & 31;
    if (w >= B_SZ) return;
    const float* hr = h1 + (size_t)w * U_SZ;
    float s = 0.f;
#pragma unroll 4
    for (int k = lane; k < U_SZ; k += 32) s += hr[k] * Wd[k];
#pragma unroll
    for (int o = 16; o > 0; o >>= 1) s += __shfl_down_sync(0xffffffffu, s, o);
    if (lane == 0) {
        float y = s + bd[0];
        x[w] = y;
        out[(size_t)w * HORIZON + d] = y;
    }
}

// per-launch state reset (graph replays must be deterministic)
__global__ void init_kernel(const float* __restrict__ dec_in)
{
    int i = blockIdx.x * blockDim.x + threadIdx.x;
    if (i < B_SZ * U_SZ) {
        g_c0[i] = 0.f;
        g_c1[i] = 0.f;
        g_h1[0][i] = 0.f;
    }
    if (i < B_SZ) g_x[i] = dec_in[i];
}

extern "C" void kernel_launch(void* const* d_in, const int* in_sizes, int n_in,
                              void* d_out, int out_size)
{
    const float* enc    = (const float*)d_in[0];
    const float* dec_in = (const float*)d_in[1];
    const float* eWx0   = (const float*)d_in[2];
    const float* eWh0   = (const float*)d_in[3];
    const float* eb0    = (const float*)d_in[4];
    const float* eWx1   = (const float*)d_in[5];
    const float* eWh1   = (const float*)d_in[6];
    const float* eb1    = (const float*)d_in[7];
    const float* dWx0   = (const float*)d_in[8];
    const float* dWh0   = (const float*)d_in[9];
    const float* db0    = (const float*)d_in[10];
    const float* dWx1   = (const float*)d_in[11];
    const float* dWh1   = (const float*)d_in[12];
    const float* db1    = (const float*)d_in[13];
    const float* Wd     = (const float*)d_in[14];
    const float* bd     = (const float*)d_in[15];
    float* out = (float*)d_out;

    float *p_out0, *p_h1, *p_c0, *p_c1, *p_dh0, *p_x, *p_zero;
    cudaGetSymbolAddress((void**)&p_out0, g_out0);
    cudaGetSymbolAddress((void**)&p_h1,   g_h1);
    cudaGetSymbolAddress((void**)&p_c0,   g_c0);
    cudaGetSymbolAddress((void**)&p_c1,   g_c1);
    cudaGetSymbolAddress((void**)&p_dh0,  g_dh0);
    cudaGetSymbolAddress((void**)&p_x,    g_x);
    cudaGetSymbolAddress((void**)&p_zero, g_zero);
    float* h1p[2]  = {p_h1,  p_h1  + (size_t)B_SZ * U_SZ};
    float* dh0p[2] = {p_dh0, p_dh0 + (size_t)B_SZ * U_SZ};

    const dim3 grid(U_SZ / 16, B_SZ / BM);   // (32, 4)

    init_kernel<<<(B_SZ * U_SZ + 255) / 256, 256>>>(dec_in);

    // ---------------- encoder layer 0 ----------------
    for (int t = 0; t < T_ENC; ++t) {
        const float* hprev = (t == 0) ? p_zero : (p_out0 + (size_t)(t - 1) * U_SZ);
        int ldah = (t == 0) ? U_SZ : (T_ENC * U_SZ);
        lstm_step<<<grid, NT>>>(
            enc + (size_t)t * F_IN, T_ENC * F_IN, F_IN, eWx0,
            hprev, ldah, U_SZ, eWh0,
            eb0, p_c0, p_out0 + (size_t)t * U_SZ, T_ENC * U_SZ);
    }

    // ---------------- encoder layer 1 ----------------
    for (int t = 0; t < T_ENC; ++t) {
        lstm_step<<<grid, NT>>>(
            p_out0 + (size_t)t * U_SZ, T_ENC * U_SZ, U_SZ, eWx1,
            h1p[t & 1], U_SZ, U_SZ, eWh1,
            eb1, p_c1, h1p[(t + 1) & 1], U_SZ);
    }

    // ---------------- decoder ----------------
    for (int d = 0; d < HORIZON; ++d) {
        const float* h0in = (d == 0) ? (p_out0 + (size_t)(T_ENC - 1) * U_SZ) : dh0p[d & 1];
        int lh0 = (d == 0) ? (T_ENC * U_SZ) : U_SZ;
        lstm_step<<<grid, NT>>>(
            p_x, 1, 1, dWx0,
            h0in, lh0, U_SZ, dWh0,
            db0, p_c0, dh0p[(d & 1) ^ 1], U_SZ);
        lstm_step<<<grid, NT>>>(
            dh0p[(d & 1) ^ 1], U_SZ, U_SZ, dWx1,
            h1p[d & 1], U_SZ, U_SZ, dWh1,
            db1, p_c1, h1p[(d + 1) & 1], U_SZ);
        proj_kernel<<<(B_SZ * 32) / 128, 128>>>(h1p[(d + 1) & 1], Wd, bd, p_x, out, d);
    }
}

// round 5
// speedup vs baseline: 1.0004x; 1.0004x over previous
#include <cuda_runtime.h>
#include <math.h>

#define B_SZ 256
#define T_ENC 336
#define F_IN 16
#define U_SZ 512
#define G4 2048
#define HORIZON 48

#define NT 256
#define BM 64
#define BN 64
#define BK 16

// ---------------- persistent device scratch (static, allocation-free) ----------------
__device__ float g_out0[(size_t)B_SZ * T_ENC * U_SZ];  // encoder layer0 h_t for all t
__device__ float g_h1[2][B_SZ * U_SZ];                 // layer1 h ping-pong
__device__ float g_c0[B_SZ * U_SZ];
__device__ float g_c1[B_SZ * U_SZ];
__device__ float g_dh0[2][B_SZ * U_SZ];
__device__ float g_x[B_SZ];
__device__ float g_zero[B_SZ * U_SZ];                  // never written: stays zero

__device__ __forceinline__ float sigf(float x) { return 1.0f / (1.0f + expf(-x)); }

// packed fp32 FMA (Blackwell): c.lo += a.lo*b.lo ; c.hi += a.hi*b.hi
#define FMA2(c, a, b) asm("fma.rn.f32x2 %0, %1, %2, %0;" : "+l"(c) : "l"(a), "l"(b))

__device__ __forceinline__ unsigned long long dup2(float v) {
    unsigned long long r;
    unsigned u = __float_as_uint(v);
    asm("mov.b64 %0, {%1, %1};" : "=l"(r) : "r"(u));
    return r;
}

// ---------------------------------------------------------------------------
// Fused LSTM step:
//   z[256, 2048] = A0[256,K0] @ W0 + A1[256,K1] @ W1 + bias
//   i,f,g,o = split(z); c = f*c + i*tanh(g); h = o*tanh(c)
// Block tile: 64 batch rows x (4 gates x 16 units); grid (32, 4).
// GEMM: 256 thr, 4x4 microtile, double-buffered smem, packed f32x2 FMA.
// B smem holds duplicated (b,b) 64-bit pairs so the inner loop has zero packing.
// ---------------------------------------------------------------------------
__global__ __launch_bounds__(NT) void lstm_step(
    const float* __restrict__ A0, int lda0, int K0, const float* __restrict__ W0,
    const float* __restrict__ A1, int lda1, int K1, const float* __restrict__ W1,
    const float* __restrict__ bias,
    float* __restrict__ c_state,
    float* __restrict__ h_out, int ldh)
{
    __shared__ float As[2][BK][BM];                    // 8 KB
    __shared__ unsigned long long Bs[2][BK][BN];       // 16 KB (dup pairs)
    __shared__ float Zs[BM][BN + 1];                   // 16.25 KB

    const int tid = threadIdx.x;
    const int block_m = blockIdx.y * BM;
    const int block_u = blockIdx.x;

    // loader mapping
    const int arow = tid >> 2;           // 0..63 : A row
    const int ak4  = (tid & 3) * 4;      // 0,4,8,12 : A k-offset (float4)
    const int bkk  = tid >> 4;           // 0..15 : B k row
    const int bn4  = (tid & 15) * 4;     // 0..60 : B tile col (float4)
    const int bwcol = (bn4 >> 4) * 512 + block_u * 16 + (bn4 & 15);

    // compute mapping: 4x4 microtile
    const int tx = tid & 15;
    const int ty = tid >> 4;
    const int n0 = tx * 4;
    const int m0 = ty * 4;

    const int tiles0 = (K0 + BK - 1) / BK;
    const int tilesT = tiles0 + (K1 + BK - 1) / BK;

    unsigned long long acc[2][4];
#pragma unroll
    for (int p = 0; p < 2; ++p)
#pragma unroll
        for (int j = 0; j < 4; ++j) acc[p][j] = 0ULL;   // (0.f, 0.f)

    auto fetch = [&](int t, float4& a, float4& w) {
        const float* A; const float* W; int lda, K, kb;
        if (t < tiles0) { A = A0; W = W0; lda = lda0; K = K0; kb = t * BK; }
        else            { A = A1; W = W1; lda = lda1; K = K1; kb = (t - tiles0) * BK; }
        const float* ab = A + (size_t)(block_m + arow) * lda + kb + ak4;
        if (kb + BK <= K) {
            a = *(const float4*)ab;
        } else {
            float t0 = (kb + ak4 + 0 < K) ? ab[0] : 0.f;
            float t1 = (kb + ak4 + 1 < K) ? ab[1] : 0.f;
            float t2 = (kb + ak4 + 2 < K) ? ab[2] : 0.f;
            float t3 = (kb + ak4 + 3 < K) ? ab[3] : 0.f;
            a = make_float4(t0, t1, t2, t3);
        }
        int kg = kb + bkk;
        if (kg < K) w = *(const float4*)(W + (size_t)kg * G4 + bwcol);
        else        w = make_float4(0.f, 0.f, 0.f, 0.f);
    };

    auto stash = [&](int s, const float4& a, const float4& w) {
        As[s][ak4 + 0][arow] = a.x;
        As[s][ak4 + 1][arow] = a.y;
        As[s][ak4 + 2][arow] = a.z;
        As[s][ak4 + 3][arow] = a.w;
        ulonglong2 p01 = make_ulonglong2(dup2(w.x), dup2(w.y));
        ulonglong2 p23 = make_ulonglong2(dup2(w.z), dup2(w.w));
        *(ulonglong2*)&Bs[s][bkk][bn4 + 0] = p01;
        *(ulonglong2*)&Bs[s][bkk][bn4 + 2] = p23;
    };

    auto compute = [&](int s) {
#pragma unroll
        for (int kk = 0; kk < BK; ++kk) {
            // a pairs: (m0,m0+1) and (m0+2,m0+3) — one LDS.128
            ulonglong2 au = *(const ulonglong2*)&As[s][kk][m0];
            // b dup pairs — two LDS.128
            ulonglong2 b01 = *(const ulonglong2*)&Bs[s][kk][n0];
            ulonglong2 b23 = *(const ulonglong2*)&Bs[s][kk][n0 + 2];
            FMA2(acc[0][0], au.x, b01.x);
            FMA2(acc[0][1], au.x, b01.y);
            FMA2(acc[0][2], au.x, b23.x);
            FMA2(acc[0][3], au.x, b23.y);
            FMA2(acc[1][0], au.y, b01.x);
            FMA2(acc[1][1], au.y, b01.y);
            FMA2(acc[1][2], au.y, b23.x);
            FMA2(acc[1][3], au.y, b23.y);
        }
    };

    // ---- double-buffered mainloop ----
    {
        float4 a, w;
        fetch(0, a, w);
        stash(0, a, w);
    }
    __syncthreads();
    int cur = 0;
    for (int t = 0; t < tilesT; ++t) {
        float4 a, w;
        const bool has_next = (t + 1 < tilesT);
        if (has_next) fetch(t + 1, a, w);
        compute(cur);
        if (has_next) {
            stash(cur ^ 1, a, w);
            __syncthreads();
            cur ^= 1;
        }
    }

    // ---- epilogue: z-tile -> smem with bias ----
    const int cwcol = (n0 >> 4) * 512 + block_u * 16 + (n0 & 15);
#pragma unroll
    for (int j = 0; j < 4; ++j) {
        float bb = bias[cwcol + j];
#pragma unroll
        for (int p = 0; p < 2; ++p) {
            unsigned long long v = acc[p][j];
            Zs[m0 + 2 * p + 0][n0 + j] = __uint_as_float((unsigned)v) + bb;
            Zs[m0 + 2 * p + 1][n0 + j] = __uint_as_float((unsigned)(v >> 32)) + bb;
        }
    }
    __syncthreads();

    // ---- gates + state update: each thread does 4 (b,u) pairs ----
    const int uo = tid & 15;
    const int gu = block_u * 16 + uo;
    const int r0 = (tid >> 4) * 4;
#pragma unroll
    for (int i = 0; i < 4; ++i) {
        int br = r0 + i;
        float zi = Zs[br][ 0 + uo];
        float zf = Zs[br][16 + uo];
        float zg = Zs[br][32 + uo];
        float zo = Zs[br][48 + uo];
        float ig = sigf(zi);
        float fg = sigf(zf);
        float gg = tanhf(zg);
        float og = sigf(zo);
        size_t ci = (size_t)(block_m + br) * U_SZ + gu;
        float cn = fg * c_state[ci] + ig * gg;
        c_state[ci] = cn;
        h_out[(size_t)(block_m + br) * ldh + gu] = og * tanhf(cn);
    }
}

// y[b] = h1[b,:] . Wd + bd ; write out[b,HORIZON] column d and next x
__global__ __launch_bounds__(128) void proj_kernel(
    const float* __restrict__ h1, const float* __restrict__ Wd,
    const float* __restrict__ bd, float* __restrict__ x,
    float* __restrict__ out, int d)
{
    int w = (blockIdx.x * blockDim.x + threadIdx.x) >> 5;
    int lane = threadIdx.x & 31;
    if (w >= B_SZ) return;
    const float* hr = h1 + (size_t)w * U_SZ;
    float s = 0.f;
#pragma unroll 4
    for (int k = lane; k < U_SZ; k += 32) s += hr[k] * Wd[k];
#pragma unroll
    for (int o = 16; o > 0; o >>= 1) s += __shfl_down_sync(0xffffffffu, s, o);
    if (lane == 0) {
        float y = s + bd[0];
        x[w] = y;
        out[(size_t)w * HORIZON + d] = y;
    }
}

// per-launch state reset (graph replays must be deterministic)
__global__ void init_kernel(const float* __restrict__ dec_in)
{
    int i = blockIdx.x * blockDim.x + threadIdx.x;
    if (i < B_SZ * U_SZ) {
        g_c0[i] = 0.f;
        g_c1[i] = 0.f;
        g_h1[0][i] = 0.f;
    }
    if (i < B_SZ) g_x[i] = dec_in[i];
}

extern "C" void kernel_launch(void* const* d_in, const int* in_sizes, int n_in,
                              void* d_out, int out_size)
{
    const float* enc    = (const float*)d_in[0];
    const float* dec_in = (const float*)d_in[1];
    const float* eWx0   = (const float*)d_in[2];
    const float* eWh0   = (const float*)d_in[3];
    const float* eb0    = (const float*)d_in[4];
    const float* eWx1   = (const float*)d_in[5];
    const float* eWh1   = (const float*)d_in[6];
    const float* eb1    = (const float*)d_in[7];
    const float* dWx0   = (const float*)d_in[8];
    const float* dWh0   = (const float*)d_in[9];
    const float* db0    = (const float*)d_in[10];
    const float* dWx1   = (const float*)d_in[11];
    const float* dWh1   = (const float*)d_in[12];
    const float* db1    = (const float*)d_in[13];
    const float* Wd     = (const float*)d_in[14];
    const float* bd     = (const float*)d_in[15];
    float* out = (float*)d_out;

    float *p_out0, *p_h1, *p_c0, *p_c1, *p_dh0, *p_x, *p_zero;
    cudaGetSymbolAddress((void**)&p_out0, g_out0);
    cudaGetSymbolAddress((void**)&p_h1,   g_h1);
    cudaGetSymbolAddress((void**)&p_c0,   g_c0);
    cudaGetSymbolAddress((void**)&p_c1,   g_c1);
    cudaGetSymbolAddress((void**)&p_dh0,  g_dh0);
    cudaGetSymbolAddress((void**)&p_x,    g_x);
    cudaGetSymbolAddress((void**)&p_zero, g_zero);
    float* h1p[2]  = {p_h1,  p_h1  + (size_t)B_SZ * U_SZ};
    float* dh0p[2] = {p_dh0, p_dh0 + (size_t)B_SZ * U_SZ};

    const dim3 grid(U_SZ / 16, B_SZ / BM);   // (32, 4)

    init_kernel<<<(B_SZ * U_SZ + 255) / 256, 256>>>(dec_in);

    // ---------------- encoder layer 0 ----------------
    for (int t = 0; t < T_ENC; ++t) {
        const float* hprev = (t == 0) ? p_zero : (p_out0 + (size_t)(t - 1) * U_SZ);
        int ldah = (t == 0) ? U_SZ : (T_ENC * U_SZ);
        lstm_step<<<grid, NT>>>(
            enc + (size_t)t * F_IN, T_ENC * F_IN, F_IN, eWx0,
            hprev, ldah, U_SZ, eWh0,
            eb0, p_c0, p_out0 + (size_t)t * U_SZ, T_ENC * U_SZ);
    }

    // ---------------- encoder layer 1 ----------------
    for (int t = 0; t < T_ENC; ++t) {
        lstm_step<<<grid, NT>>>(
            p_out0 + (size_t)t * U_SZ, T_ENC * U_SZ, U_SZ, eWx1,
            h1p[t & 1], U_SZ, U_SZ, eWh1,
            eb1, p_c1, h1p[(t + 1) & 1], U_SZ);
    }

    // ---------------- decoder ----------------
    for (int d = 0; d < HORIZON; ++d) {
        const float* h0in = (d == 0) ? (p_out0 + (size_t)(T_ENC - 1) * U_SZ) : dh0p[d & 1];
        int lh0 = (d == 0) ? (T_ENC * U_SZ) : U_SZ;
        lstm_step<<<grid, NT>>>(
            p_x, 1, 1, dWx0,
            h0in, lh0, U_SZ, dWh0,
            db0, p_c0, dh0p[(d & 1) ^ 1], U_SZ);
        lstm_step<<<grid, NT>>>(
            dh0p[(d & 1) ^ 1], U_SZ, U_SZ, dWx1,
            h1p[d & 1], U_SZ, U_SZ, dWh1,
            db1, p_c1, h1p[(d + 1) & 1], U_SZ);
        proj_kernel<<<(B_SZ * 32) / 128, 128>>>(h1p[(d + 1) & 1], Wd, bd, p_x, out, d);
    }
}

// round 7
// speedup vs baseline: 4.0825x; 4.0810x over previous
#include <cuda_runtime.h>
#include <cuda_bf16.h>
#include <math.h>
#include <stdint.h>

#define B_SZ 256
#define T_ENC 336
#define U_SZ 512
#define HORIZON 48

// ---------------- persistent device scratch ----------------
// W images: [ntile 32][chunk T][64 n][16 k] bf16 blobs (2KB each)
__device__ __align__(256) __nv_bfloat16 g_We0h[32 * 33 * 1024], g_We0l[32 * 33 * 1024]; // K=528
__device__ __align__(256) __nv_bfloat16 g_We1h[32 * 64 * 1024], g_We1l[32 * 64 * 1024]; // K=1024
__device__ __align__(256) __nv_bfloat16 g_Wd0h[32 * 32 * 1024], g_Wd0l[32 * 32 * 1024]; // K=512
__device__ __align__(256) __nv_bfloat16 g_Wd1h[32 * 64 * 1024], g_Wd1l[32 * 64 * 1024]; // K=1024
// state images: [mtile 4][chunk 32][64 m][16 k] per slot (131072 elem = 256KB)
#define SLOT_E 131072
__device__ __align__(256) __nv_bfloat16 g_o0h[(size_t)T_ENC * SLOT_E], g_o0l[(size_t)T_ENC * SLOT_E];
__device__ __align__(256) __nv_bfloat16 g_h1h[2 * SLOT_E], g_h1l[2 * SLOT_E];
__device__ __align__(256) __nv_bfloat16 g_d0h[2 * SLOT_E], g_d0l[2 * SLOT_E];
__device__ __align__(256) __nv_bfloat16 g_zh[SLOT_E], g_zl[SLOT_E];     // never written: zero
// encoder x images: per t: [mtile 4][1 chunk][64][16] = 4096 elem
__device__ __align__(256) __nv_bfloat16 g_xih[(size_t)T_ENC * 4096], g_xil[(size_t)T_ENC * 4096];
__device__ float g_c0[B_SZ * U_SZ], g_c1[B_SZ * U_SZ], g_h1f[B_SZ * U_SZ];
__device__ float g_biasp[4 * 2048], g_xrowp[2048], g_x[B_SZ];

__device__ __forceinline__ float sigf(float x) { return 1.0f / (1.0f + expf(-x)); }

// ---------------- PTX helpers (all sm_80-baseline) ----------------
__device__ __forceinline__ uint32_t smem_u32(const void* p) {
    uint32_t a;
    asm("{ .reg .u64 t; cvta.to.shared.u64 t, %1; cvt.u32.u64 %0, t; }" : "=r"(a) : "l"(p));
    return a;
}
__device__ __forceinline__ void cp16(uint32_t dst, const void* src) {
    asm volatile("cp.async.cg.shared.global [%0], [%1], 16;" :: "r"(dst), "l"(src) : "memory");
}
__device__ __forceinline__ void cp_commit() { asm volatile("cp.async.commit_group;" ::: "memory"); }
__device__ __forceinline__ void cp_wait(int rem) {
    if (rem <= 0)      asm volatile("cp.async.wait_group 0;" ::: "memory");
    else if (rem == 1) asm volatile("cp.async.wait_group 1;" ::: "memory");
    else               asm volatile("cp.async.wait_group 2;" ::: "memory");
}
__device__ __forceinline__ void ldmx4(uint32_t* r, uint32_t addr) {
    asm volatile("ldmatrix.sync.aligned.m8n8.x4.shared.b16 {%0,%1,%2,%3}, [%4];"
                 : "=r"(r[0]), "=r"(r[1]), "=r"(r[2]), "=r"(r[3]) : "r"(addr));
}
#define MMA(d, a, b0, b1)                                                          \
    asm volatile("mma.sync.aligned.m16n8k16.row.col.f32.bf16.bf16.f32 "            \
                 "{%0,%1,%2,%3}, {%4,%5,%6,%7}, {%8,%9}, {%0,%1,%2,%3};"           \
                 : "+f"(d[0]), "+f"(d[1]), "+f"(d[2]), "+f"(d[3])                  \
                 : "r"(a[0]), "r"(a[1]), "r"(a[2]), "r"(a[3]), "r"(b0), "r"(b1))

// smem swizzle: blob unit i (16B units, i = row*2 + seg) -> i ^ ((i>>3)&1)
__device__ __forceinline__ uint32_t swz(uint32_t i) { return i ^ ((i >> 3) & 1); }

// ---------------------------------------------------------------------------
// Fused LSTM step, HMMA version. Grid (32 ntiles, 4 mtiles), 256 threads.
// A segs: [mtile][chunk][64 m][16 k] blobs; W: [ntile][chunk][64 n][16 k].
// ---------------------------------------------------------------------------
__global__ __launch_bounds__(256) void lstm_mma(
    const __nv_bfloat16* __restrict__ a0h, const __nv_bfloat16* __restrict__ a0l, int nk0,
    const __nv_bfloat16* __restrict__ a1h, const __nv_bfloat16* __restrict__ a1l, int nk1,
    const __nv_bfloat16* __restrict__ wh, const __nv_bfloat16* __restrict__ wl,
    const float* __restrict__ biasp,
    const float* __restrict__ xrowp, const float* __restrict__ xvec,
    float* __restrict__ c_state,
    __nv_bfloat16* __restrict__ outh, __nv_bfloat16* __restrict__ outl,
    float* __restrict__ h1f)
{
    __shared__ __align__(1024) unsigned char smem[32768];   // 4 stages x 8KB; aliased as Zs later
    const uint32_t sb = smem_u32(smem);
    const int tid = threadIdx.x, lane = tid & 31, wid = tid >> 5;
    const int ntile = blockIdx.x, mtile = blockIdx.y;
    const int T = nk0 + nk1;

    // loader mapping: 4 blobs (Ah, Al, Bh, Bl) x 128 16B-units; 256 thr x 2 units
    const int which = tid >> 6;
    const int i0 = tid & 63;

    // ldmatrix source offsets
    const int wm = wid & 1, wn = wid >> 1;
    const int arow = wm * 32 + (lane & 15);
    const int aseg = lane >> 4;
    const uint32_t offA0 = (uint32_t)((arow * 2 + (aseg ^ ((arow >> 2) & 1))) * 16);
    const int arow1 = arow + 16;
    const uint32_t offA1 = (uint32_t)((arow1 * 2 + (aseg ^ ((arow1 >> 2) & 1))) * 16);
    const int brow = wn * 16 + (lane & 7) + ((lane >> 4) << 3);
    const int bseg = (lane >> 3) & 1;
    const uint32_t offB = (uint32_t)((brow * 2 + (bseg ^ ((brow >> 2) & 1))) * 16);

    float acc[2][2][4];
#pragma unroll
    for (int im = 0; im < 2; ++im)
#pragma unroll
        for (int jn = 0; jn < 2; ++jn)
#pragma unroll
            for (int q = 0; q < 4; ++q) acc[im][jn][q] = 0.f;

    auto load_chunk = [&](int t) {
        const __nv_bfloat16* src;
        if (which < 2) {
            if (t < nk0) {
                size_t b = ((size_t)mtile * nk0 + t) * 1024;
                src = (which == 0 ? a0h : a0l) + b;
            } else {
                size_t b = ((size_t)mtile * nk1 + (t - nk0)) * 1024;
                src = (which == 0 ? a1h : a1l) + b;
            }
        } else {
            size_t b = ((size_t)ntile * T + t) * 1024;
            src = (which == 2 ? wh : wl) + b;
        }
        uint32_t dstb = sb + (t & 3) * 8192 + which * 2048;
#pragma unroll
        for (int r = 0; r < 2; ++r) {
            uint32_t i = (uint32_t)(i0 + 64 * r);
            cp16(dstb + swz(i) * 16, src + i * 8);
        }
        cp_commit();
    };

    load_chunk(0); load_chunk(1); load_chunk(2);

    for (int t = 0; t < T; ++t) {
        int rem = T - 1 - t; if (rem > 2) rem = 2;
        cp_wait(rem);
        __syncthreads();
        uint32_t s = sb + (t & 3) * 8192;
        uint32_t ah0[4], ah1[4], al0[4], al1[4], bh[4], bl[4];
        ldmx4(ah0, s + offA0);
        ldmx4(ah1, s + offA1);
        ldmx4(al0, s + 2048 + offA0);
        ldmx4(al1, s + 2048 + offA1);
        ldmx4(bh, s + 4096 + offB);
        ldmx4(bl, s + 6144 + offB);
#pragma unroll
        for (int jn = 0; jn < 2; ++jn) {
            MMA(acc[0][jn], ah0, bh[2 * jn], bh[2 * jn + 1]);
            MMA(acc[1][jn], ah1, bh[2 * jn], bh[2 * jn + 1]);
            MMA(acc[0][jn], ah0, bl[2 * jn], bl[2 * jn + 1]);
            MMA(acc[1][jn], ah1, bl[2 * jn], bl[2 * jn + 1]);
            MMA(acc[0][jn], al0, bh[2 * jn], bh[2 * jn + 1]);
            MMA(acc[1][jn], al1, bh[2 * jn], bh[2 * jn + 1]);
        }
        if (t + 3 < T) load_chunk(t + 3);
    }

    // ---- epilogue: accum frags -> smem z-tile (alias stage buffers) ----
    __syncthreads();
    float* Z = (float*)smem;                 // [64][68]
    const int g = lane >> 2, cc = (lane & 3) * 2;
#pragma unroll
    for (int im = 0; im < 2; ++im)
#pragma unroll
        for (int jn = 0; jn < 2; ++jn) {
            int r0 = wm * 32 + im * 16 + g;
            int c0 = wn * 16 + jn * 8 + cc;
            Z[r0 * 68 + c0]       = acc[im][jn][0];
            Z[r0 * 68 + c0 + 1]   = acc[im][jn][1];
            Z[(r0 + 8) * 68 + c0]     = acc[im][jn][2];
            Z[(r0 + 8) * 68 + c0 + 1] = acc[im][jn][3];
        }
    __syncthreads();

    // ---- gates + state update: 256 thr x 4 (m,u) pairs ----
#pragma unroll
    for (int q = 0; q < 4; ++q) {
        int idx = tid + 256 * q;
        int m_loc = idx >> 4, uo = idx & 15;
        int m = mtile * 64 + m_loc;
        int pbase = ntile * 64 + uo;
        float zi = Z[m_loc * 68 + uo]       + biasp[pbase];
        float zf = Z[m_loc * 68 + 16 + uo]  + biasp[pbase + 16];
        float zg = Z[m_loc * 68 + 32 + uo]  + biasp[pbase + 32];
        float zo = Z[m_loc * 68 + 48 + uo]  + biasp[pbase + 48];
        if (xrowp) {
            float xm = xvec[m];
            zi += xm * xrowp[pbase];
            zf += xm * xrowp[pbase + 16];
            zg += xm * xrowp[pbase + 32];
            zo += xm * xrowp[pbase + 48];
        }
        float ig = sigf(zi), fg = sigf(zf), gg = tanhf(zg), og = sigf(zo);
        int u = ntile * 16 + uo;
        int ci = m * U_SZ + u;
        float cn = fg * c_state[ci] + ig * gg;
        c_state[ci] = cn;
        float h = og * tanhf(cn);
        __nv_bfloat16 hh = __float2bfloat16(h);
        __nv_bfloat16 hl = __float2bfloat16(h - __bfloat162float(hh));
        size_t off = (((size_t)mtile * 32 + ntile) * 64 + m_loc) * 16 + uo;
        outh[off] = hh;
        outl[off] = hl;
        if (h1f) h1f[ci] = h;
    }
}

// ---------------- preprocessing ----------------
// W image: k<kx from Wx, k>=kx from Wh[(k-whs)]; permuted cols; [ntile][chunk][64][16]
__global__ void wprep(const float* __restrict__ Wx, int kx,
                      const float* __restrict__ Wh, int whs, int K, int T,
                      __nv_bfloat16* __restrict__ dh, __nv_bfloat16* __restrict__ dl)
{
    int i = blockIdx.x * 256 + threadIdx.x;
    if (i >= K * 2048) return;
    int k = i >> 11, orig = i & 2047;
    int gate = orig >> 9, rem = orig & 511;
    int ntile = rem >> 4, uo = rem & 15;
    int nloc = gate * 16 + uo;
    float w = (k < kx) ? Wx[(size_t)k * 2048 + orig]
                       : Wh[(size_t)(k - whs) * 2048 + orig];
    __nv_bfloat16 h = __float2bfloat16(w);
    __nv_bfloat16 l = __float2bfloat16(w - __bfloat162float(h));
    size_t off = (((size_t)ntile * T + (k >> 4)) * 64 + nloc) * 16 + (k & 15);
    dh[off] = h;
    dl[off] = l;
}

// encoder x images: [t][mtile][64][16]
__global__ void xprep(const float* __restrict__ enc,
                      __nv_bfloat16* __restrict__ dh, __nv_bfloat16* __restrict__ dl)
{
    int i = blockIdx.x * 256 + threadIdx.x;
    if (i >= T_ENC * B_SZ * 16) return;
    int t = i >> 12, r = i & 4095, m = r >> 4, k = r & 15;
    float v = enc[(size_t)m * (T_ENC * 16) + t * 16 + k];
    __nv_bfloat16 h = __float2bfloat16(v);
    __nv_bfloat16 l = __float2bfloat16(v - __bfloat162float(h));
    size_t off = (((size_t)t * 4 + (m >> 6)) * 64 + (m & 63)) * 16 + k;
    dh[off] = h;
    dl[off] = l;
}

__global__ void bprep(const float* b0, const float* b1, const float* b2, const float* b3,
                      const float* dWx0)
{
    int i = blockIdx.x * 256 + threadIdx.x;
    if (i >= 5 * 2048) return;
    int g = i >> 11, pcol = i & 2047;
    int orig = ((pcol >> 4) & 3) * 512 + (pcol >> 6) * 16 + (pcol & 15);
    if (g == 4) g_xrowp[pcol] = dWx0[orig];
    else {
        const float* s = (g == 0) ? b0 : (g == 1) ? b1 : (g == 2) ? b2 : b3;
        g_biasp[g * 2048 + pcol] = s[orig];
    }
}

__global__ void init_kernel(const float* __restrict__ dec_in)
{
    int i = blockIdx.x * 256 + threadIdx.x;
    if (i < B_SZ * U_SZ) { g_c0[i] = 0.f; g_c1[i] = 0.f; }
    if (i < B_SZ) g_x[i] = dec_in[i];
}

__global__ __launch_bounds__(128) void proj_kernel(
    const float* __restrict__ h1, const float* __restrict__ Wd,
    const float* __restrict__ bd, float* __restrict__ x,
    float* __restrict__ out, int d)
{
    int w = (blockIdx.x * blockDim.x + threadIdx.x) >> 5;
    int lane = threadIdx.x & 31;
    if (w >= B_SZ) return;
    const float* hr = h1 + (size_t)w * U_SZ;
    float s = 0.f;
#pragma unroll 4
    for (int k = lane; k < U_SZ; k += 32) s += hr[k] * Wd[k];
#pragma unroll
    for (int o = 16; o > 0; o >>= 1) s += __shfl_down_sync(0xffffffffu, s, o);
    if (lane == 0) {
        float y = s + bd[0];
        x[w] = y;
        out[(size_t)w * HORIZON + d] = y;
    }
}

extern "C" void kernel_launch(void* const* d_in, const int* in_sizes, int n_in,
                              void* d_out, int out_size)
{
    const float* enc  = (const float*)d_in[0];
    const float* dcin = (const float*)d_in[1];
    const float* eWx0 = (const float*)d_in[2];
    const float* eWh0 = (const float*)d_in[3];
    const float* eb0  = (const float*)d_in[4];
    const float* eWx1 = (const float*)d_in[5];
    const float* eWh1 = (const float*)d_in[6];
    const float* eb1  = (const float*)d_in[7];
    const float* dWx0 = (const float*)d_in[8];
    const float* dWh0 = (const float*)d_in[9];
    const float* db0  = (const float*)d_in[10];
    const float* dWx1 = (const float*)d_in[11];
    const float* dWh1 = (const float*)d_in[12];
    const float* db1  = (const float*)d_in[13];
    const float* Wd   = (const float*)d_in[14];
    const float* bd   = (const float*)d_in[15];
    float* out = (float*)d_out;

    __nv_bfloat16 *We0h, *We0l, *We1h, *We1l, *Wd0h, *Wd0l, *Wd1h, *Wd1l;
    __nv_bfloat16 *o0h, *o0l, *xih, *xil, *h1h, *h1l, *d0h, *d0l, *zh, *zl;
    float *c0, *c1, *h1f, *biasp, *xrowp, *xv;
    cudaGetSymbolAddress((void**)&We0h, g_We0h); cudaGetSymbolAddress((void**)&We0l, g_We0l);
    cudaGetSymbolAddress((void**)&We1h, g_We1h); cudaGetSymbolAddress((void**)&We1l, g_We1l);
    cudaGetSymbolAddress((void**)&Wd0h, g_Wd0h); cudaGetSymbolAddress((void**)&Wd0l, g_Wd0l);
    cudaGetSymbolAddress((void**)&Wd1h, g_Wd1h); cudaGetSymbolAddress((void**)&Wd1l, g_Wd1l);
    cudaGetSymbolAddress((void**)&o0h, g_o0h);   cudaGetSymbolAddress((void**)&o0l, g_o0l);
    cudaGetSymbolAddress((void**)&xih, g_xih);   cudaGetSymbolAddress((void**)&xil, g_xil);
    cudaGetSymbolAddress((void**)&h1h, g_h1h);   cudaGetSymbolAddress((void**)&h1l, g_h1l);
    cudaGetSymbolAddress((void**)&d0h, g_d0h);   cudaGetSymbolAddress((void**)&d0l, g_d0l);
    cudaGetSymbolAddress((void**)&zh, g_zh);     cudaGetSymbolAddress((void**)&zl, g_zl);
    cudaGetSymbolAddress((void**)&c0, g_c0);     cudaGetSymbolAddress((void**)&c1, g_c1);
    cudaGetSymbolAddress((void**)&h1f, g_h1f);
    cudaGetSymbolAddress((void**)&biasp, g_biasp);
    cudaGetSymbolAddress((void**)&xrowp, g_xrowp);
    cudaGetSymbolAddress((void**)&xv, g_x);

    const dim3 grid(32, 4);

    // ---- preprocessing (captured; deterministic every replay) ----
    wprep<<<(528 * 2048 + 255) / 256, 256>>>(eWx0, 16, eWh0, 16, 528, 33, We0h, We0l);
    wprep<<<(1024 * 2048 + 255) / 256, 256>>>(eWx1, 512, eWh1, 512, 1024, 64, We1h, We1l);
    wprep<<<(512 * 2048 + 255) / 256, 256>>>(nullptr, 0, dWh0, 0, 512, 32, Wd0h, Wd0l);
    wprep<<<(1024 * 2048 + 255) / 256, 256>>>(dWx1, 512, dWh1, 512, 1024, 64, Wd1h, Wd1l);
    xprep<<<(T_ENC * B_SZ * 16 + 255) / 256, 256>>>(enc, xih, xil);
    bprep<<<(5 * 2048 + 255) / 256, 256>>>(eb0, eb1, db0, db1, dWx0);
    init_kernel<<<(B_SZ * U_SZ + 255) / 256, 256>>>(dcin);

    // ---- encoder layer 0: x chunk (k0..15) + h (k16..527) vs We0 (K=528) ----
    for (int t = 0; t < T_ENC; ++t) {
        const __nv_bfloat16* hh = (t == 0) ? zh : o0h + (size_t)(t - 1) * SLOT_E;
        const __nv_bfloat16* hl = (t == 0) ? zl : o0l + (size_t)(t - 1) * SLOT_E;
        lstm_mma<<<grid, 256>>>(
            xih + (size_t)t * 4096, xil + (size_t)t * 4096, 1,
            hh, hl, 32,
            We0h, We0l, biasp + 0 * 2048, nullptr, nullptr, c0,
            o0h + (size_t)t * SLOT_E, o0l + (size_t)t * SLOT_E, nullptr);
    }

    // ---- encoder layer 1 (K=1024: out0 | h1) ----
    for (int t = 0; t < T_ENC; ++t) {
        const __nv_bfloat16* hh = (t == 0) ? zh : h1h + (size_t)(t & 1) * SLOT_E;
        const __nv_bfloat16* hl = (t == 0) ? zl : h1l + (size_t)(t & 1) * SLOT_E;
        lstm_mma<<<grid, 256>>>(
            o0h + (size_t)t * SLOT_E, o0l + (size_t)t * SLOT_E, 32,
            hh, hl, 32,
            We1h, We1l, biasp + 1 * 2048, nullptr, nullptr, c1,
            h1h + (size_t)((t + 1) & 1) * SLOT_E, h1l + (size_t)((t + 1) & 1) * SLOT_E, nullptr);
    }

    // ---- decoder ----
    for (int d = 0; d < HORIZON; ++d) {
        const __nv_bfloat16* h0h = (d == 0) ? o0h + (size_t)(T_ENC - 1) * SLOT_E
                                            : d0h + (size_t)(d & 1) * SLOT_E;
        const __nv_bfloat16* h0l = (d == 0) ? o0l + (size_t)(T_ENC - 1) * SLOT_E
                                            : d0l + (size_t)(d & 1) * SLOT_E;
        // layer 0 (K=512, rank-1 x added exactly in epilogue)
        lstm_mma<<<grid, 256>>>(
            h0h, h0l, 32,
            nullptr, nullptr, 0,
            Wd0h, Wd0l, biasp + 2 * 2048, xrowp, xv, c0,
            d0h + (size_t)((d & 1) ^ 1) * SLOT_E, d0l + (size_t)((d & 1) ^ 1) * SLOT_E, nullptr);
        // layer 1 (K=1024: d0 | h1)
        lstm_mma<<<grid, 256>>>(
            d0h + (size_t)((d & 1) ^ 1) * SLOT_E, d0l + (size_t)((d & 1) ^ 1) * SLOT_E, 32,
            h1h + (size_t)(d & 1) * SLOT_E, h1l + (size_t)(d & 1) * SLOT_E, 32,
            Wd1h, Wd1l, biasp + 3 * 2048, nullptr, nullptr, c1,
            h1h + (size_t)((d + 1) & 1) * SLOT_E, h1l + (size_t)((d + 1) & 1) * SLOT_E, h1f);
        proj_kernel<<<(B_SZ * 32) / 128, 128>>>(h1f, Wd, bd, xv, out, d);
    }
}

// round 8
// speedup vs baseline: 5.1414x; 1.2594x over previous
#include <cuda_runtime.h>
#include <cuda_bf16.h>
#include <math.h>
#include <stdint.h>

#define B_SZ 256
#define T_ENC 336
#define U_SZ 512
#define HORIZON 48

// ---------------- persistent device scratch ----------------
// W images: [ntile 32][blob16 T16][64 n][16 k] bf16 blobs (2KB each)
__device__ __align__(256) __nv_bfloat16 g_We0h[32 * 34 * 1024], g_We0l[32 * 34 * 1024]; // K=544 (x16|pad16|Wh512)
__device__ __align__(256) __nv_bfloat16 g_We1h[32 * 64 * 1024], g_We1l[32 * 64 * 1024]; // K=1024
__device__ __align__(256) __nv_bfloat16 g_Wd0h[32 * 32 * 1024], g_Wd0l[32 * 32 * 1024]; // K=512
__device__ __align__(256) __nv_bfloat16 g_Wd1h[32 * 64 * 1024], g_Wd1l[32 * 64 * 1024]; // K=1024
// state images: [mtile 4][blob16 32][64 m][16 k] per slot
#define SLOT_E 131072
__device__ __align__(256) __nv_bfloat16 g_o0h[(size_t)T_ENC * SLOT_E], g_o0l[(size_t)T_ENC * SLOT_E];
__device__ __align__(256) __nv_bfloat16 g_h1h[2 * SLOT_E], g_h1l[2 * SLOT_E];
__device__ __align__(256) __nv_bfloat16 g_d0h[2 * SLOT_E], g_d0l[2 * SLOT_E];
__device__ __align__(256) __nv_bfloat16 g_zh[SLOT_E], g_zl[SLOT_E];     // never written: zero
// encoder x images: per t: [mtile 4][2 blobs][64][16]; blob1 never written (zero)
__device__ __align__(256) __nv_bfloat16 g_xih[(size_t)T_ENC * 8192], g_xil[(size_t)T_ENC * 8192];
__device__ float g_c0[B_SZ * U_SZ], g_c1[B_SZ * U_SZ];
__device__ float g_biasp[4 * 2048], g_xrowp[2048], g_xb[2][B_SZ];

__device__ __forceinline__ float sigf(float x) { return 1.0f / (1.0f + expf(-x)); }

// ---------------- PTX helpers ----------------
__device__ __forceinline__ uint32_t smem_u32(const void* p) {
    uint32_t a;
    asm("{ .reg .u64 t; cvta.to.shared.u64 t, %1; cvt.u32.u64 %0, t; }" : "=r"(a) : "l"(p));
    return a;
}
__device__ __forceinline__ void cp16(uint32_t dst, const void* src) {
    asm volatile("cp.async.cg.shared.global [%0], [%1], 16;" :: "r"(dst), "l"(src) : "memory");
}
__device__ __forceinline__ void cp_commit() { asm volatile("cp.async.commit_group;" ::: "memory"); }
__device__ __forceinline__ void cp_wait(int rem) {
    if (rem <= 0)      asm volatile("cp.async.wait_group 0;" ::: "memory");
    else if (rem == 1) asm volatile("cp.async.wait_group 1;" ::: "memory");
    else               asm volatile("cp.async.wait_group 2;" ::: "memory");
}
__device__ __forceinline__ void ldmx4(uint32_t* r, uint32_t addr) {
    asm volatile("ldmatrix.sync.aligned.m8n8.x4.shared.b16 {%0,%1,%2,%3}, [%4];"
                 : "=r"(r[0]), "=r"(r[1]), "=r"(r[2]), "=r"(r[3]) : "r"(addr));
}
#define MMA(d, a, b0, b1)                                                          \
    asm volatile("mma.sync.aligned.m16n8k16.row.col.f32.bf16.bf16.f32 "            \
                 "{%0,%1,%2,%3}, {%4,%5,%6,%7}, {%8,%9}, {%0,%1,%2,%3};"           \
                 : "+f"(d[0]), "+f"(d[1]), "+f"(d[2]), "+f"(d[3])                  \
                 : "r"(a[0]), "r"(a[1]), "r"(a[2]), "r"(a[3]), "r"(b0), "r"(b1))

__device__ __forceinline__ uint32_t swz(uint32_t i) { return i ^ ((i >> 3) & 1); }

// ---------------------------------------------------------------------------
struct Job {
    const __nv_bfloat16 *a0h, *a0l;  int nk0;   // 16k blobs per mtile (seg0)
    const __nv_bfloat16 *a1h, *a1l;  int nk1;   // seg1
    const __nv_bfloat16 *wh, *wl;    int T16;   // nk0+nk1
    const float *biasp;
    const float *xrowp, *xvec, *bdp;            // dec-l0: rank-1 x, bd
    float *youtprev;                            // dec-l0: out col d-1 (stride 48), may be null
    float *xinit;                               // dec-l0: x_{d+1} := bd0
    const float *projWd;                        // dec-l1: projection weights
    float *xnext;                               // dec-l1: atomicAdd target (= y_d)
    float *c;                                   // cell state [B*U]
    __nv_bfloat16 *outh, *outl;                 // next-step h tile images
};

// Fused LSTM step (HMMA). Grid (32 ntiles, 4 mtiles, njobs), 256 threads.
// 32-wide k chunks, 4-stage 64KB cp.async pipeline, prefetch 3.
__global__ __launch_bounds__(256) void lstm_mma(Job j0, Job j1)
{
    extern __shared__ __align__(1024) unsigned char smem[];   // 65536
    const Job jb = (blockIdx.z == 0) ? j0 : j1;
    const uint32_t sb = smem_u32(smem);
    const int tid = threadIdx.x, lane = tid & 31, wid = tid >> 5;
    const int ntile = blockIdx.x, mtile = blockIdx.y;
    const int T32 = jb.T16 >> 1;

    const int which = tid >> 6;        // quarter: 0 Ah, 1 Al, 2 Bh, 3 Bl
    const int i0 = tid & 63;

    // ldmatrix offsets (blob-local, 2KB blobs of [64][16] bf16)
    const int wm = wid & 1, wn = wid >> 1;
    const int arow = wm * 32 + (lane & 15);
    const int aseg = lane >> 4;
    const uint32_t offA0 = (uint32_t)((arow * 2 + (aseg ^ ((arow >> 2) & 1))) * 16);
    const int arow1 = arow + 16;
    const uint32_t offA1 = (uint32_t)((arow1 * 2 + (aseg ^ ((arow1 >> 2) & 1))) * 16);
    const int brow = wn * 16 + (lane & 7) + ((lane >> 4) << 3);
    const int bseg = (lane >> 3) & 1;
    const uint32_t offB = (uint32_t)((brow * 2 + (bseg ^ ((brow >> 2) & 1))) * 16);

    float acc[2][2][4];
#pragma unroll
    for (int im = 0; im < 2; ++im)
#pragma unroll
        for (int jn = 0; jn < 2; ++jn)
#pragma unroll
            for (int q = 0; q < 4; ++q) acc[im][jn][q] = 0.f;

    auto load_chunk = [&](int t32) {
        uint32_t dstb = sb + (uint32_t)(t32 & 3) * 16384 + (uint32_t)which * 4096;
#pragma unroll
        for (int r = 0; r < 4; ++r) {
            int u = i0 + 64 * r;               // 0..255 within quarter
            int sub = u >> 7, jj = u & 127;
            int cb = 2 * t32 + sub;            // 16k blob index
            const __nv_bfloat16* src;
            if (which < 2) {
                bool s0 = cb < jb.nk0;
                const __nv_bfloat16* base = (which == 0) ? (s0 ? jb.a0h : jb.a1h)
                                                         : (s0 ? jb.a0l : jb.a1l);
                int nk = s0 ? jb.nk0 : jb.nk1;
                int cc = s0 ? cb : cb - jb.nk0;
                src = base + ((size_t)mtile * nk + cc) * 1024;
            } else {
                src = ((which == 2) ? jb.wh : jb.wl) + ((size_t)ntile * jb.T16 + cb) * 1024;
            }
            cp16(dstb + (uint32_t)(sub * 2048) + swz((uint32_t)jj) * 16, src + jj * 8);
        }
        cp_commit();
    };

    load_chunk(0); load_chunk(1); load_chunk(2);

    for (int t = 0; t < T32; ++t) {
        int rem = T32 - 1 - t; if (rem > 2) rem = 2;
        cp_wait(rem);
        __syncthreads();
        if (t + 3 < T32) load_chunk(t + 3);
        uint32_t s = sb + (uint32_t)(t & 3) * 16384;
#pragma unroll
        for (int ks = 0; ks < 2; ++ks) {
            uint32_t s2 = s + (uint32_t)ks * 2048;
            uint32_t ah0[4], ah1[4], al0[4], al1[4], bh[4], bl[4];
            ldmx4(ah0, s2 + offA0);
            ldmx4(ah1, s2 + offA1);
            ldmx4(al0, s2 + 4096 + offA0);
            ldmx4(al1, s2 + 4096 + offA1);
            ldmx4(bh, s2 + 8192 + offB);
            ldmx4(bl, s2 + 12288 + offB);
#pragma unroll
            for (int jn = 0; jn < 2; ++jn) {
                MMA(acc[0][jn], ah0, bh[2 * jn], bh[2 * jn + 1]);
                MMA(acc[1][jn], ah1, bh[2 * jn], bh[2 * jn + 1]);
                MMA(acc[0][jn], ah0, bl[2 * jn], bl[2 * jn + 1]);
                MMA(acc[1][jn], ah1, bl[2 * jn], bl[2 * jn + 1]);
                MMA(acc[0][jn], al0, bh[2 * jn], bh[2 * jn + 1]);
                MMA(acc[1][jn], al1, bh[2 * jn], bh[2 * jn + 1]);
            }
        }
    }

    // ---- epilogue: accum frags -> smem z-tile (alias stage buffers) ----
    __syncthreads();
    float* Z = (float*)smem;                 // [64][68]
    const int g = lane >> 2, cc2 = (lane & 3) * 2;
#pragma unroll
    for (int im = 0; im < 2; ++im)
#pragma unroll
        for (int jn = 0; jn < 2; ++jn) {
            int r0 = wm * 32 + im * 16 + g;
            int c0 = wn * 16 + jn * 8 + cc2;
            Z[r0 * 68 + c0]           = acc[im][jn][0];
            Z[r0 * 68 + c0 + 1]       = acc[im][jn][1];
            Z[(r0 + 8) * 68 + c0]     = acc[im][jn][2];
            Z[(r0 + 8) * 68 + c0 + 1] = acc[im][jn][3];
        }
    __syncthreads();

    const float bd0 = jb.bdp ? jb.bdp[0] : 0.f;

#pragma unroll
    for (int q = 0; q < 4; ++q) {
        int idx = tid + 256 * q;
        int m_loc = idx >> 4, uo = idx & 15;
        int m = mtile * 64 + m_loc;
        int pbase = ntile * 64 + uo;
        float zi = Z[m_loc * 68 + uo]       + jb.biasp[pbase];
        float zf = Z[m_loc * 68 + 16 + uo]  + jb.biasp[pbase + 16];
        float zg = Z[m_loc * 68 + 32 + uo]  + jb.biasp[pbase + 32];
        float zo = Z[m_loc * 68 + 48 + uo]  + jb.biasp[pbase + 48];
        float xm = 0.f;
        if (jb.xrowp) {
            xm = jb.xvec[m];
            zi += xm * jb.xrowp[pbase];
            zf += xm * jb.xrowp[pbase + 16];
            zg += xm * jb.xrowp[pbase + 32];
            zo += xm * jb.xrowp[pbase + 48];
        }
        float ig = sigf(zi), fg = sigf(zf), gg = tanhf(zg), og = sigf(zo);
        int u = ntile * 16 + uo;
        int ci = m * U_SZ + u;
        float cn = fg * jb.c[ci] + ig * gg;
        jb.c[ci] = cn;
        float h = og * tanhf(cn);
        __nv_bfloat16 hh = __float2bfloat16(h);
        __nv_bfloat16 hl = __float2bfloat16(h - __bfloat162float(hh));
        size_t off = (((size_t)mtile * 32 + ntile) * 64 + m_loc) * 16 + uo;
        jb.outh[off] = hh;
        jb.outl[off] = hl;

        if (jb.xrowp && uo == 0 && ntile == 0) {
            if (jb.youtprev) jb.youtprev[m * HORIZON] = xm;   // out column d-1 = y_{d-1}
            jb.xinit[m] = bd0;                                 // seed next-x accumulator
        }
        if (jb.projWd) {
            float p = h * jb.projWd[u];
            p += __shfl_xor_sync(0xffffffffu, p, 8, 16);
            p += __shfl_xor_sync(0xffffffffu, p, 4, 16);
            p += __shfl_xor_sync(0xffffffffu, p, 2, 16);
            p += __shfl_xor_sync(0xffffffffu, p, 1, 16);
            if (uo == 0) atomicAdd(&jb.xnext[m], p);
        }
    }
}

// ---------------- preprocessing ----------------
// W image: k<kx from Wx; k>=whs from Wh[k-whs]; else zero. Permuted cols.
__global__ void wprep(const float* __restrict__ Wx, int kx,
                      const float* __restrict__ Wh, int whs, int K, int T16,
                      __nv_bfloat16* __restrict__ dh, __nv_bfloat16* __restrict__ dl)
{
    int i = blockIdx.x * 256 + threadIdx.x;
    if (i >= K * 2048) return;
    int k = i >> 11, orig = i & 2047;
    int gate = orig >> 9, rem = orig & 511;
    int ntile = rem >> 4, uo = rem & 15;
    int nloc = gate * 16 + uo;
    float w = 0.f;
    if (k < kx)       w = Wx[(size_t)k * 2048 + orig];
    else if (k >= whs) w = Wh[(size_t)(k - whs) * 2048 + orig];
    __nv_bfloat16 h = __float2bfloat16(w);
    __nv_bfloat16 l = __float2bfloat16(w - __bfloat162float(h));
    size_t off = (((size_t)ntile * T16 + (k >> 4)) * 64 + nloc) * 16 + (k & 15);
    dh[off] = h;
    dl[off] = l;
}

// encoder x images: [t][mtile][2 blobs][64][16]; only blob 0 written
__global__ void xprep(const float* __restrict__ enc,
                      __nv_bfloat16* __restrict__ dh, __nv_bfloat16* __restrict__ dl)
{
    int i = blockIdx.x * 256 + threadIdx.x;
    if (i >= T_ENC * B_SZ * 16) return;
    int t = i >> 12, r = i & 4095, m = r >> 4, k = r & 15;
    float v = enc[(size_t)m * (T_ENC * 16) + t * 16 + k];
    __nv_bfloat16 h = __float2bfloat16(v);
    __nv_bfloat16 l = __float2bfloat16(v - __bfloat162float(h));
    size_t off = (((size_t)t * 4 + (m >> 6)) * 2) * 1024 + (size_t)(m & 63) * 16 + k;
    dh[off] = h;
    dl[off] = l;
}

__global__ void bprep(const float* b0, const float* b1, const float* b2, const float* b3,
                      const float* dWx0)
{
    int i = blockIdx.x * 256 + threadIdx.x;
    if (i >= 5 * 2048) return;
    int g = i >> 11, pcol = i & 2047;
    int orig = ((pcol >> 4) & 3) * 512 + (pcol >> 6) * 16 + (pcol & 15);
    if (g == 4) g_xrowp[pcol] = dWx0[orig];
    else {
        const float* s = (g == 0) ? b0 : (g == 1) ? b1 : (g == 2) ? b2 : b3;
        g_biasp[g * 2048 + pcol] = s[orig];
    }
}

__global__ void init_kernel(const float* __restrict__ dec_in)
{
    int i = blockIdx.x * 256 + threadIdx.x;
    if (i < B_SZ * U_SZ) { g_c0[i] = 0.f; g_c1[i] = 0.f; }
    if (i < B_SZ) g_xb[0][i] = dec_in[i];
}

__global__ void final_kernel(float* __restrict__ out)
{
    int m = threadIdx.x;
    if (m < B_SZ) out[m * HORIZON + (HORIZON - 1)] = g_xb[HORIZON & 1][m];
}

extern "C" void kernel_launch(void* const* d_in, const int* in_sizes, int n_in,
                              void* d_out, int out_size)
{
    const float* enc  = (const float*)d_in[0];
    const float* dcin = (const float*)d_in[1];
    const float* eWx0 = (const float*)d_in[2];
    const float* eWh0 = (const float*)d_in[3];
    const float* eb0  = (const float*)d_in[4];
    const float* eWx1 = (const float*)d_in[5];
    const float* eWh1 = (const float*)d_in[6];
    const float* eb1  = (const float*)d_in[7];
    const float* dWx0 = (const float*)d_in[8];
    const float* dWh0 = (const float*)d_in[9];
    const float* db0  = (const float*)d_in[10];
    const float* dWx1 = (const float*)d_in[11];
    const float* dWh1 = (const float*)d_in[12];
    const float* db1  = (const float*)d_in[13];
    const float* Wd   = (const float*)d_in[14];
    const float* bd   = (const float*)d_in[15];
    float* out = (float*)d_out;

    cudaFuncSetAttribute(lstm_mma, cudaFuncAttributeMaxDynamicSharedMemorySize, 65536);

    __nv_bfloat16 *We0h, *We0l, *We1h, *We1l, *Wd0h, *Wd0l, *Wd1h, *Wd1l;
    __nv_bfloat16 *o0h, *o0l, *xih, *xil, *h1h, *h1l, *d0h, *d0l, *zh, *zl;
    float *c0, *c1, *biasp, *xrowp, *xb;
    cudaGetSymbolAddress((void**)&We0h, g_We0h); cudaGetSymbolAddress((void**)&We0l, g_We0l);
    cudaGetSymbolAddress((void**)&We1h, g_We1h); cudaGetSymbolAddress((void**)&We1l, g_We1l);
    cudaGetSymbolAddress((void**)&Wd0h, g_Wd0h); cudaGetSymbolAddress((void**)&Wd0l, g_Wd0l);
    cudaGetSymbolAddress((void**)&Wd1h, g_Wd1h); cudaGetSymbolAddress((void**)&Wd1l, g_Wd1l);
    cudaGetSymbolAddress((void**)&o0h, g_o0h);   cudaGetSymbolAddress((void**)&o0l, g_o0l);
    cudaGetSymbolAddress((void**)&xih, g_xih);   cudaGetSymbolAddress((void**)&xil, g_xil);
    cudaGetSymbolAddress((void**)&h1h, g_h1h);   cudaGetSymbolAddress((void**)&h1l, g_h1l);
    cudaGetSymbolAddress((void**)&d0h, g_d0h);   cudaGetSymbolAddress((void**)&d0l, g_d0l);
    cudaGetSymbolAddress((void**)&zh, g_zh);     cudaGetSymbolAddress((void**)&zl, g_zl);
    cudaGetSymbolAddress((void**)&c0, g_c0);     cudaGetSymbolAddress((void**)&c1, g_c1);
    cudaGetSymbolAddress((void**)&biasp, g_biasp);
    cudaGetSymbolAddress((void**)&xrowp, g_xrowp);
    cudaGetSymbolAddress((void**)&xb, g_xb);

    auto mkjob = [&](const __nv_bfloat16* a0hh, const __nv_bfloat16* a0ll, int nk0,
                     const __nv_bfloat16* a1hh, const __nv_bfloat16* a1ll, int nk1,
                     const __nv_bfloat16* whh, const __nv_bfloat16* wll, int T16,
                     const float* bp, float* cst,
                     __nv_bfloat16* oh, __nv_bfloat16* ol) {
        Job j;
        j.a0h = a0hh; j.a0l = a0ll; j.nk0 = nk0;
        j.a1h = a1hh; j.a1l = a1ll; j.nk1 = nk1;
        j.wh = whh; j.wl = wll; j.T16 = T16;
        j.biasp = bp;
        j.xrowp = nullptr; j.xvec = nullptr; j.bdp = nullptr;
        j.youtprev = nullptr; j.xinit = nullptr;
        j.projWd = nullptr; j.xnext = nullptr;
        j.c = cst; j.outh = oh; j.outl = ol;
        return j;
    };

    // ---- preprocessing ----
    wprep<<<(544 * 2048 + 255) / 256, 256>>>(eWx0, 16, eWh0, 32, 544, 34, We0h, We0l);
    wprep<<<(1024 * 2048 + 255) / 256, 256>>>(eWx1, 512, eWh1, 512, 1024, 64, We1h, We1l);
    wprep<<<(512 * 2048 + 255) / 256, 256>>>(nullptr, 0, dWh0, 0, 512, 32, Wd0h, Wd0l);
    wprep<<<(1024 * 2048 + 255) / 256, 256>>>(dWx1, 512, dWh1, 512, 1024, 64, Wd1h, Wd1l);
    xprep<<<(T_ENC * B_SZ * 16 + 255) / 256, 256>>>(enc, xih, xil);
    bprep<<<(5 * 2048 + 255) / 256, 256>>>(eb0, eb1, db0, db1, dWx0);
    init_kernel<<<(B_SZ * U_SZ + 255) / 256, 256>>>(dcin);

    // ---- encoder: fused l0(s) + l1(s-1), s = 0..336 ----
    for (int s = 0; s <= T_ENC; ++s) {
        Job jobs[2];
        int nj = 0;
        if (s < T_ENC) {   // layer0 step s
            const __nv_bfloat16* hh = (s == 0) ? zh : o0h + (size_t)(s - 1) * SLOT_E;
            const __nv_bfloat16* hl = (s == 0) ? zl : o0l + (size_t)(s - 1) * SLOT_E;
            jobs[nj++] = mkjob(xih + (size_t)s * 8192, xil + (size_t)s * 8192, 2,
                               hh, hl, 32, We0h, We0l, 34,
                               biasp + 0 * 2048, c0,
                               o0h + (size_t)s * SLOT_E, o0l + (size_t)s * SLOT_E);
        }
        if (s >= 1) {      // layer1 step s-1
            int t = s - 1;
            const __nv_bfloat16* hh = (t == 0) ? zh : h1h + (size_t)(t & 1) * SLOT_E;
            const __nv_bfloat16* hl = (t == 0) ? zl : h1l + (size_t)(t & 1) * SLOT_E;
            jobs[nj++] = mkjob(o0h + (size_t)t * SLOT_E, o0l + (size_t)t * SLOT_E, 32,
                               hh, hl, 32, We1h, We1l, 64,
                               biasp + 1 * 2048, c1,
                               h1h + (size_t)((t + 1) & 1) * SLOT_E,
                               h1l + (size_t)((t + 1) & 1) * SLOT_E);
        }
        dim3 grid(32, 4, nj);
        lstm_mma<<<grid, 256, 65536>>>(jobs[0], jobs[nj - 1]);
    }

    // ---- decoder ----
    for (int d = 0; d < HORIZON; ++d) {
        // layer 0 (K=512) + rank-1 x + bookkeeping
        {
            const __nv_bfloat16* h0hh = (d == 0) ? o0h + (size_t)(T_ENC - 1) * SLOT_E
                                                 : d0h + (size_t)(d & 1) * SLOT_E;
            const __nv_bfloat16* h0ll = (d == 0) ? o0l + (size_t)(T_ENC - 1) * SLOT_E
                                                 : d0l + (size_t)(d & 1) * SLOT_E;
            Job j = mkjob(h0hh, h0ll, 32, nullptr, nullptr, 0,
                          Wd0h, Wd0l, 32, biasp + 2 * 2048, c0,
                          d0h + (size_t)((d & 1) ^ 1) * SLOT_E,
                          d0l + (size_t)((d & 1) ^ 1) * SLOT_E);
            j.xrowp = xrowp;
            j.xvec  = xb + (size_t)(d & 1) * B_SZ;
            j.bdp   = bd;
            j.youtprev = (d == 0) ? nullptr : out + (d - 1);
            j.xinit = xb + (size_t)((d + 1) & 1) * B_SZ;
            lstm_mma<<<dim3(32, 4, 1), 256, 65536>>>(j, j);
        }
        // layer 1 (K=1024) + fused projection
        {
            Job j = mkjob(d0h + (size_t)((d & 1) ^ 1) * SLOT_E,
                          d0l + (size_t)((d & 1) ^ 1) * SLOT_E, 32,
                          h1h + (size_t)(d & 1) * SLOT_E,
                          h1l + (size_t)(d & 1) * SLOT_E, 32,
                          Wd1h, Wd1l, 64, biasp + 3 * 2048, c1,
                          h1h + (size_t)((d + 1) & 1) * SLOT_E,
                          h1l + (size_t)((d + 1) & 1) * SLOT_E);
            j.projWd = Wd;
            j.xnext  = xb + (size_t)((d + 1) & 1) * B_SZ;
            lstm_mma<<<dim3(32, 4, 1), 256, 65536>>>(j, j);
        }
    }
    final_kernel<<<1, 256>>>(out);
}